// round 4
// baseline (speedup 1.0000x reference)
#include <cuda_runtime.h>

#define HIDDEN 128
#define THREADS 256
#define NPAIR 2            // packed f32x2 pairs per thread (4 rays/thread)

typedef unsigned long long ull;

__device__ __forceinline__ float ex2f_(float x) {
    float y; asm("ex2.approx.f32 %0, %1;" : "=f"(y) : "f"(x)); return y;
}
__device__ __forceinline__ ull pk2(float lo, float hi) {
    ull r; asm("mov.b64 %0, {%1, %2};" : "=l"(r) : "f"(lo), "f"(hi)); return r;
}
__device__ __forceinline__ void upk2(ull v, float& lo, float& hi) {
    asm("mov.b64 {%0, %1}, %2;" : "=f"(lo), "=f"(hi) : "l"(v));
}
__device__ __forceinline__ ull ffma2(ull a, ull b, ull c) {
    ull d; asm("fma.rn.f32x2 %0, %1, %2, %3;" : "=l"(d) : "l"(a), "l"(b), "l"(c)); return d;
}

// Degree-6 poly for ln(1+e), e in [0,1], Horner directly in e.
// Derived from the u=2e-1 economized Taylor poly by exact binomial expansion.
// Endpoint-verified: p(0)=3.8e-6, p(0.5)=ln(1.5)+-2e-7, p(1)=ln(2)+-1e-7.
#define PB0  0.0000038232f
#define PB1  0.9998071004f
#define PB2 -0.4971104576f
#define PB3  0.3149249096f
#define PB4 -0.1890210048f
#define PB5  0.0816135904f
#define PB6 -0.0170705728f

struct __align__(16) WMain { ull w0, w1, w2, b; };  // W1 rows+b1, *log2e, dup {w,w}
struct __align__(16) WOut  { ull w2p, w2l; };       // {W2,W2}, {W2*ln2, W2*ln2}

__global__ __launch_bounds__(THREADS, 4)
void raymarch_kernel(const float* __restrict__ r,
                     const float* __restrict__ pivot,
                     const float* __restrict__ W1,
                     const float* __restrict__ b1,
                     const float* __restrict__ W2,
                     const float* __restrict__ b2,
                     const int*   __restrict__ n_iter_p,
                     float* __restrict__ out,
                     int n_rays)
{
    __shared__ WMain s_w[HIDDEN];   // 4 KB
    __shared__ WOut  s_o[HIDDEN];   // 2 KB

    const float L2E = 1.4426950408889634f;
    const float LN2 = 0.6931471805599453f;

    const int tid = threadIdx.x;
    if (tid < HIDDEN) {
        float a0 = W1[tid] * L2E;
        float a1 = W1[HIDDEN + tid] * L2E;
        float a2 = W1[2 * HIDDEN + tid] * L2E;
        float bb = b1[tid] * L2E;
        float w2 = W2[tid];
        s_w[tid].w0  = pk2(a0, a0);
        s_w[tid].w1  = pk2(a1, a1);
        s_w[tid].w2  = pk2(a2, a2);
        s_w[tid].b   = pk2(bb, bb);
        s_o[tid].w2p = pk2(w2, w2);
        s_o[tid].w2l = pk2(w2 * LN2, w2 * LN2);
    }
    __syncthreads();

    const float pv0 = pivot[0], pv1 = pivot[1], pv2 = pivot[2];
    const float b2v = b2[0];
    const int n_it = n_iter_p ? *n_iter_p : 20;

    const int base = (blockIdx.x * THREADS + tid) * (2 * NPAIR);

    float rn0[2 * NPAIR], dx[2 * NPAIR], dy[2 * NPAIR], dz[2 * NPAIR];
    float alpha[2 * NPAIR];
    bool valid[2 * NPAIR];

    #pragma unroll
    for (int k = 0; k < 2 * NPAIR; ++k) {
        const int i = base + k;
        valid[k] = (i < n_rays);
        float4 rv = valid[k] ? reinterpret_cast<const float4*>(r)[i]
                             : make_float4(1.f, 0.f, 0.f, 0.f);
        float inv = rsqrtf(rv.x * rv.x + rv.y * rv.y + rv.z * rv.z + rv.w * rv.w);
        rn0[k] = rv.x * inv;
        dx[k]  = rv.y * inv;
        dy[k]  = rv.z * inv;
        dz[k]  = rv.w * inv;
        alpha[k] = 0.f;
    }

    const ull C0 = pk2(PB0, PB0), C1 = pk2(PB1, PB1), C2 = pk2(PB2, PB2),
              C3 = pk2(PB3, PB3), C4 = pk2(PB4, PB4), C5 = pk2(PB5, PB5),
              C6 = pk2(PB6, PB6);

    for (int it = 0; it < n_it; ++it) {
        ull p0d[NPAIR], p1d[NPAIR], p2d[NPAIR];
        ull accP[NPAIR], accM[NPAIR];
        float x0[2 * NPAIR];

        #pragma unroll
        for (int q = 0; q < NPAIR; ++q) {
            const int k = 2 * q;
            p0d[q] = pk2(fmaf(alpha[k], dx[k], pv0), fmaf(alpha[k+1], dx[k+1], pv0));
            p1d[q] = pk2(fmaf(alpha[k], dy[k], pv1), fmaf(alpha[k+1], dy[k+1], pv1));
            p2d[q] = pk2(fmaf(alpha[k], dz[k], pv2), fmaf(alpha[k+1], dz[k+1], pv2));
            accP[q] = 0ull;
            accM[q] = 0ull;
            x0[k]   = alpha[k]   * rn0[k];
            x0[k+1] = alpha[k+1] * rn0[k+1];
        }

        #pragma unroll 2
        for (int j = 0; j < HIDDEN; ++j) {
            const ulonglong2* wp = reinterpret_cast<const ulonglong2*>(&s_w[j]);
            ulonglong2 q0 = wp[0];   // w0, w1
            ulonglong2 q1 = wp[1];   // w2row, b
            ulonglong2 q2 = *reinterpret_cast<const ulonglong2*>(&s_o[j]);  // w2p, w2l

            #pragma unroll
            for (int q = 0; q < NPAIR; ++q) {
                // aL = (x . W1 + b1) * log2e, packed over 2 rays
                ull aL = ffma2(p0d[q], q0.x, ffma2(p1d[q], q0.y, ffma2(p2d[q], q1.x, q1.y)));
                float alo, ahi; upk2(aL, alo, ahi);

                // e = 2^(-|aL|) = exp(-|arg|)
                float elo = ex2f_(-fabsf(alo));
                float ehi = ex2f_(-fabsf(ahi));
                ull e2 = pk2(elo, ehi);

                // ln(1+e): Horner in e
                ull p = ffma2(C6, e2, C5);
                p = ffma2(p, e2, C4);
                p = ffma2(p, e2, C3);
                p = ffma2(p, e2, C2);
                p = ffma2(p, e2, C1);
                p = ffma2(p, e2, C0);

                // relu part, packed
                ull m = pk2(fmaxf(alo, 0.f), fmaxf(ahi, 0.f));

                accP[q] = ffma2(q2.x, p, accP[q]);   // W2 * ln(1+e)
                accM[q] = ffma2(q2.y, m, accM[q]);   // (W2*ln2) * max(aL,0)
            }
        }

        #pragma unroll
        for (int q = 0; q < NPAIR; ++q) {
            const int k = 2 * q;
            float pl, ph, ml, mh;
            upk2(accP[q], pl, ph);
            upk2(accM[q], ml, mh);
            float s0 = (pl + ml) + b2v;
            float s1 = (ph + mh) + b2v;
            float a0 = fabsf(s0);
            float a1 = fabsf(s1);
            float ext0 = fmaxf(fmaxf(s0, x0[k]   - a0), -a0 - x0[k]);
            float ext1 = fmaxf(fmaxf(s1, x0[k+1] - a1), -a1 - x0[k+1]);
            alpha[k]   -= ext0;
            alpha[k+1] -= ext1;
        }
    }

    #pragma unroll
    for (int k = 0; k < 2 * NPAIR; ++k) {
        if (valid[k]) {
            const int i = base + k;
            out[3 * i + 0] = fmaf(alpha[k], dx[k], pv0);
            out[3 * i + 1] = fmaf(alpha[k], dy[k], pv1);
            out[3 * i + 2] = fmaf(alpha[k], dz[k], pv2);
        }
    }
}

extern "C" void kernel_launch(void* const* d_in, const int* in_sizes, int n_in,
                              void* d_out, int out_size)
{
    const float* r     = (const float*)d_in[0];
    const float* pivot = (const float*)d_in[1];
    const float* W1    = (const float*)d_in[2];
    const float* b1    = (const float*)d_in[3];
    const float* W2    = (const float*)d_in[4];
    const float* b2    = (const float*)d_in[5];
    const int*   n_it  = (n_in > 6) ? (const int*)d_in[6] : nullptr;

    const int n_rays = in_sizes[0] / 4;
    const int rays_per_block = THREADS * 2 * NPAIR;
    const int blocks = (n_rays + rays_per_block - 1) / rays_per_block;

    raymarch_kernel<<<blocks, THREADS>>>(r, pivot, W1, b1, W2, b2, n_it,
                                         (float*)d_out, n_rays);
}